// round 14
// baseline (speedup 1.0000x reference)
#include <cuda_runtime.h>
#include <cuda_bf16.h>
#include <math.h>
#include <stdint.h>

// Problem constants
#define TT 2048
#define BB 8
#define DD 1024
#define NS 1024
#define NBLK 128
#define MM (TT*BB)        // 16384 projection rows
#define KP 3072           // K' = 3*D  (bf16x3 split concatenated along K)
#define NP 3072           // N' = 3*N_STATE (k,v,q concatenated along N)

// Scratch (device globals: no cudaMalloc allowed)
__device__ __nv_bfloat16 g_A[(size_t)MM * KP];   // [Ah | Ah | Al]
__device__ __nv_bfloat16 g_B[(size_t)NP * KP];   // rows: Wk,Wv,Wq; cols: [Bh | Bl | Bh]
__device__ float         g_P[(size_t)MM * NP];   // cols 0-1023=k, 1024-2047=v, 2048-3071=q

// GEMM tiling: 128x64 tile, 256 threads, 3 stages -> 72KB -> 3 CTAs/SM
#define GTM 128
#define GTN 64
#define GCK 64
#define G_NCH (KP / GCK)                   // 48
#define STG_BYTES ((GTM + GTN) * GCK * 2)  // 24576 per stage
#define G_SMEM (3 * STG_BYTES)             // 73728
#define N_NT (NP / GTN)                    // 48 N-tiles per slab
#define N_MT (MM / GTM)                    // 128 M-slabs (16 timesteps each)
#define N_TILES (N_MT * N_NT)              // 6144
#define SCANB 32
#define NBLOCKS 444                        // 148 SMs x 3 slots, one wave

#define XU ((size_t)MM * DD / 4)           // float4 units in x
#define WU ((size_t)3 * NS * DD / 4)       // float4 units in weights

__device__ uint32_t g_tile_ctr;
__device__ uint32_t g_done[N_MT];

// ---------------------------------------------------------------------------
// Helpers
// ---------------------------------------------------------------------------
static __device__ __forceinline__ uint32_t smem_u32(const void* p) {
    uint32_t a;
    asm("{ .reg .u64 t; cvta.to.shared.u64 t, %1; cvt.u32.u64 %0, t; }" : "=r"(a) : "l"(p));
    return a;
}
#define SWZ(off) ((off) ^ (((off) >> 3) & 0x70))

#define CP_ASYNC16(saddr, gaddr) \
    asm volatile("cp.async.cg.shared.global [%0], [%1], 16;" :: "r"(saddr), "l"(gaddr))
#define CP_ASYNC4(saddr, gaddr) \
    asm volatile("cp.async.ca.shared.global [%0], [%1], 4;" :: "r"(saddr), "l"(gaddr))
#define CP_COMMIT() asm volatile("cp.async.commit_group;" ::: "memory")
#define CP_WAIT(n)  asm volatile("cp.async.wait_group %0;" :: "n"(n) : "memory")

#define LDSM_X4(r0, r1, r2, r3, addr) \
    asm volatile("ldmatrix.sync.aligned.m8n8.x4.shared.b16 {%0,%1,%2,%3}, [%4];" \
                 : "=r"(r0), "=r"(r1), "=r"(r2), "=r"(r3) : "r"(addr))

static __device__ __forceinline__ void mma16816(float* d, const uint32_t* a,
                                                const uint32_t* b) {
    asm volatile(
        "mma.sync.aligned.m16n8k16.row.col.f32.bf16.bf16.f32 "
        "{%0,%1,%2,%3}, {%4,%5,%6,%7}, {%8,%9}, {%0,%1,%2,%3};"
        : "+f"(d[0]), "+f"(d[1]), "+f"(d[2]), "+f"(d[3])
        : "r"(a[0]), "r"(a[1]), "r"(a[2]), "r"(a[3]), "r"(b[0]), "r"(b[1]));
}

static __device__ __forceinline__ uint32_t ld_acq(const uint32_t* p) {
    uint32_t v;
    asm volatile("ld.acquire.gpu.global.u32 %0, [%1];" : "=r"(v) : "l"(p) : "memory");
    return v;
}

// Fast-math primitives (MUFU)
static __device__ __forceinline__ float f_tanh(float x)  { float r; asm("tanh.approx.f32 %0, %1;"  : "=f"(r) : "f"(x)); return r; }
static __device__ __forceinline__ float f_rsqrt(float x) { float r; asm("rsqrt.approx.f32 %0, %1;" : "=f"(r) : "f"(x)); return r; }

static __device__ __forceinline__ float dot8(const float* a, const float* b) {
    float p = a[0]*b[0]; p = fmaf(a[1],b[1],p); p = fmaf(a[2],b[2],p); p = fmaf(a[3],b[3],p);
    float q = a[4]*b[4]; q = fmaf(a[5],b[5],q); q = fmaf(a[6],b[6],q); q = fmaf(a[7],b[7],q);
    return p + q;
}

// ---------------------------------------------------------------------------
// Conversion (merged x + weights): fp32 -> bf16 hi/lo split, K-concatenated
// ---------------------------------------------------------------------------
static __device__ __forceinline__ uint2 pack4(const float* f, bool lo_part) {
    unsigned short h[4];
#pragma unroll
    for (int j = 0; j < 4; j++) {
        __nv_bfloat16 hi = __float2bfloat16(f[j]);
        if (!lo_part) h[j] = __bfloat16_as_ushort(hi);
        else          h[j] = __bfloat16_as_ushort(__float2bfloat16(f[j] - __bfloat162float(hi)));
    }
    uint2 r;
    r.x = (uint32_t)h[0] | ((uint32_t)h[1] << 16);
    r.y = (uint32_t)h[2] | ((uint32_t)h[3] << 16);
    return r;
}

__global__ void __launch_bounds__(256)
convert_all_kernel(const float* __restrict__ X, const float* __restrict__ Wk,
                   const float* __restrict__ Wv, const float* __restrict__ Wq) {
    // reset producer-consumer state for this graph replay
    if (blockIdx.x == 0) {
        if (threadIdx.x == 0) g_tile_ctr = 0;
        if (threadIdx.x < N_MT) g_done[threadIdx.x] = 0;
    }
    size_t i = (size_t)blockIdx.x * 256 + threadIdx.x;
    if (i < XU) {
        size_t e = i * 4;
        size_t m = e / DD;
        int    c = (int)(e % DD);
        float4 a = *(const float4*)(X + e);
        float f[4] = {a.x, a.y, a.z, a.w};
        uint2 hp = pack4(f, false);
        uint2 lp = pack4(f, true);
        __nv_bfloat16* row = g_A + m * KP;
        *(uint2*)(row + c)        = hp;
        *(uint2*)(row + c + DD)   = hp;
        *(uint2*)(row + c + 2*DD) = lp;
    } else {
        size_t e = (i - XU) * 4;
        int    w = (int)(e / ((size_t)NS * DD));
        size_t r = e % ((size_t)NS * DD);
        const float* W = (w == 0) ? Wk : ((w == 1) ? Wv : Wq);
        size_t n = r / DD;
        int    c = (int)(r % DD);
        float4 a = *(const float4*)(W + r);
        float f[4] = {a.x, a.y, a.z, a.w};
        uint2 hp = pack4(f, false);
        uint2 lp = pack4(f, true);
        __nv_bfloat16* row = g_B + ((size_t)w * NS + n) * KP;
        *(uint2*)(row + c)        = hp;
        *(uint2*)(row + c + DD)   = lp;
        *(uint2*)(row + c + 2*DD) = hp;
    }
}

// ---------------------------------------------------------------------------
// FUSED persistent kernel, 444 blocks (148 SMs x 3 residency slots).
// Blocks 0..31: scan consumers (8 warps, 32 chains each, spread 1/SM).
// Blocks 32..443: persistent GEMM workers, 128x64 tiles, 3 CTAs/SM.
// GEMM never waits on scan => no deadlock possible under any placement.
// ---------------------------------------------------------------------------
#define SDEPTH 16

__global__ void __launch_bounds__(256, 3)
fused_kernel(float* __restrict__ out, int write_sf)
{
    extern __shared__ char smem[];
    __shared__ int s_tile;
    const int tid = threadIdx.x;

    if (blockIdx.x >= SCANB) {
        // =================== GEMM worker (128x64 tile, 8 warps) =============
        const uint32_t sb = smem_u32(smem);
        const int wid = tid >> 5;
        const int lid = tid & 31;
        const int wm = wid & 1;          // 2 M-slabs of 64
        const int wn = wid >> 1;         // 4 N-slabs of 16
        const int lrow  = (lid & 7) + ((lid >> 3) & 1) * 8;
        const int chalf = lid >> 4;

        for (;;) {
            __syncthreads();             // smem stages + s_tile safe to reuse
            if (tid == 0) s_tile = (int)atomicAdd(&g_tile_ctr, 1u);
            __syncthreads();
            const int tile = s_tile;
            if (tile >= N_TILES) break;
            const int mt = tile / N_NT;
            const int nt = tile - mt * N_NT;
            const size_t bm = (size_t)mt * GTM;
            const size_t bn = (size_t)nt * GTN;
            const __nv_bfloat16* Abase = g_A + bm * KP;
            const __nv_bfloat16* Bbase = g_B + bn * KP;

            auto issue_stage = [&](int i) {
                const uint32_t abuf = sb + (i % 3) * STG_BYTES;
                const uint32_t bbuf = abuf + GTM * GCK * 2;   // +16384
                const __nv_bfloat16* As = Abase + i * GCK;
                const __nv_bfloat16* Bs = Bbase + i * GCK;
#pragma unroll
                for (int u = 0; u < 4; u++) {                  // A: 1024 units
                    int unit = tid + u * 256;
                    int r = unit >> 3, c = unit & 7;
                    CP_ASYNC16(abuf + SWZ(r * 128 + c * 16),
                               (const char*)(As + (size_t)r * KP + c * 8));
                }
#pragma unroll
                for (int u = 0; u < 2; u++) {                  // B: 512 units
                    int unit = tid + u * 256;
                    int r = unit >> 3, c = unit & 7;
                    CP_ASYNC16(bbuf + SWZ(r * 128 + c * 16),
                               (const char*)(Bs + (size_t)r * KP + c * 8));
                }
                CP_COMMIT();
            };

            issue_stage(0);
            issue_stage(1);

            float acc[4][2][4];
#pragma unroll
            for (int i = 0; i < 4; i++)
#pragma unroll
                for (int j = 0; j < 2; j++)
#pragma unroll
                    for (int r = 0; r < 4; r++) acc[i][j][r] = 0.0f;

            for (int it = 0; it < G_NCH; it++) {
                CP_WAIT(1);
                __syncthreads();
                if (it + 2 < G_NCH) issue_stage(it + 2);
                else CP_COMMIT();

                const uint32_t abuf = sb + (it % 3) * STG_BYTES;
                const uint32_t bbuf = abuf + GTM * GCK * 2;

#pragma unroll
                for (int s = 0; s < 4; s++) {
                    const int ch = 2 * s + chalf;
                    uint32_t a[4][4];
#pragma unroll
                    for (int mf = 0; mf < 4; mf++) {
                        uint32_t addr = abuf + SWZ((wm * 64 + mf * 16 + lrow) * 128 + ch * 16);
                        LDSM_X4(a[mf][0], a[mf][1], a[mf][2], a[mf][3], addr);
                    }
                    uint32_t b[4];
                    {
                        uint32_t addr = bbuf + SWZ((wn * 16 + lrow) * 128 + ch * 16);
                        LDSM_X4(b[0], b[1], b[2], b[3], addr);
                    }
#pragma unroll
                    for (int mf = 0; mf < 4; mf++) {
#pragma unroll
                        for (int nf = 0; nf < 2; nf++) {
                            uint32_t bb_[2] = { b[nf], b[nf + 2] };
                            mma16816(acc[mf][nf], a[mf], bb_);
                        }
                    }
                }
            }

            // epilogue + release
            const int r0 = lid >> 2;
            const int cp = (lid & 3) * 2;
#pragma unroll
            for (int mf = 0; mf < 4; mf++) {
#pragma unroll
                for (int nf = 0; nf < 2; nf++) {
                    float* dst = g_P + (bm + wm * 64 + mf * 16 + r0) * (size_t)NP
                                     + bn + wn * 16 + nf * 8 + cp;
                    *(float2*)dst = make_float2(acc[mf][nf][0], acc[mf][nf][1]);
                    *(float2*)(dst + 8 * NP) = make_float2(acc[mf][nf][2], acc[mf][nf][3]);
                }
            }
            __threadfence();
            __syncthreads();
            if (tid == 0)
                asm volatile("red.release.gpu.global.add.u32 [%0], 1;"
                             :: "l"(&g_done[mt]) : "memory");
        }
        return;
    }

    // =================== scan consumer: 32 chains, 8 warps ==================
    const int sblk = blockIdx.x;     // 0..31
    const int w    = tid >> 5;       // 0..7
    const int l    = tid & 31;
    const int lane = tid & 7;
    const int c    = sblk * 32 + (tid >> 3);
    const int b    = sblk >> 2;
    const int nb   = c & 127;
    const int col0 = (sblk & 3) * 256 + w * 32;
    const size_t pstep = (size_t)BB * NP;

    float* dsm = (float*)smem;
    const uint32_t rb = smem_u32(smem) + w * 384;   // warp slice: 96 floats
    const float* myslice = dsm + w * 96;
    const int ch8 = l & 24;

    const float* src = g_P + (size_t)b * NP + col0;

    auto issue = [&](int t) {
        const float* sp = src + (size_t)t * pstep;
        uint32_t st = rb + (t & (SDEPTH - 1)) * 3072;   // 8 warps * 384B per stage
        CP_ASYNC4(st + l * 4,       (const char*)(sp + l));
        CP_ASYNC4(st + 128 + l * 4, (const char*)(sp + NS + l));
        CP_ASYNC4(st + 256 + l * 4, (const char*)(sp + 2 * NS + l));
        CP_COMMIT();
    };

    auto load_prep = [&](int t, float* kn, float* qc, float& vv) {
        const float* fs = myslice + (t & (SDEPTH - 1)) * 768;
        float4 k0 = *(const float4*)(fs + ch8);
        float4 k1 = *(const float4*)(fs + ch8 + 4);
        float4 q0 = *(const float4*)(fs + 64 + ch8);
        float4 q1 = *(const float4*)(fs + 64 + ch8 + 4);
        vv = fs[32 + ch8 + lane];
        float kc[8] = {k0.x,k0.y,k0.z,k0.w,k1.x,k1.y,k1.z,k1.w};
        float ss  = dot8(kc, kc);
        float inv = f_rsqrt(ss + 1e-12f);   // == 1/(||k||+1e-6) to ~3.5e-7 rel
#pragma unroll
        for (int j = 0; j < 8; j++) kn[j] = kc[j] * inv;
        qc[0]=q0.x; qc[1]=q0.y; qc[2]=q0.z; qc[3]=q0.w;
        qc[4]=q1.x; qc[5]=q1.y; qc[6]=q1.z; qc[7]=q1.w;
    };

    int ready = -1;
    auto wait_slab = [&](int t) {
        int need = t >> 4;           // 16 timesteps per 128-row slab
        if (need > ready) {
            while (ld_acq(&g_done[need]) < (uint32_t)N_NT) __nanosleep(64);
            ready = need;
        }
    };

    float* op = out + (size_t)b * NS + nb * 8 + lane;
    const int ostride = BB * NS;

    float S[8];
#pragma unroll
    for (int j = 0; j < 8; j++) S[j] = 0.0f;

    // prologue: wait first slabs, then 14 stages in flight
    wait_slab(13);
    for (int st = 0; st < 14; st++) issue(st);
    CP_WAIT(13);
    __syncwarp();

    float knA[8], qcA[8], vvA, knB[8], qcB[8], vvB;
    load_prep(0, knA, qcA, vvA);

    auto step = [&](int t, const float* kn, const float* qc, float vv,
                    float* knN, float* qcN, float& vvN) {
        if (t + 14 < TT) { wait_slab(t + 14); issue(t + 14); }
        else CP_COMMIT();

        // --- S critical chain: retrieve -> delta -> HW tanh ---
        float r = dot8(S, kn);
        float delta = vv - r;
#pragma unroll
        for (int j = 0; j < 8; j++)
            S[j] = f_tanh(fmaf(delta, kn[j], S[j]));

        // --- fill tanh latency: advance pipeline + prep t+1 ---
        CP_WAIT(13);
        __syncwarp();
        if (t + 1 < TT) load_prep(t + 1, knN, qcN, vvN);

        // --- output for t: silu sigmoid via HW tanh ---
        float sq  = dot8(S, qc);
        float sig = fmaf(0.5f, f_tanh(0.5f * sq), 0.5f);
        op[(size_t)t * ostride] = sq * sq * sig;
    };

    for (int t = 0; t < TT; t += 2) {
        step(t,     knA, qcA, vvA, knB, qcB, vvB);
        step(t + 1, knB, qcB, vvB, knA, qcA, vvA);
    }

    if (write_sf) {
        float* sf = out + (size_t)MM * NS + (size_t)c * 64 + lane * 8;
#pragma unroll
        for (int j = 0; j < 8; j++) sf[j] = S[j];
    }
}

// ---------------------------------------------------------------------------
extern "C" void kernel_launch(void* const* d_in, const int* in_sizes, int n_in,
                              void* d_out, int out_size)
{
    (void)in_sizes; (void)n_in;
    const float* x  = (const float*)d_in[0];
    const float* wk = (const float*)d_in[1];
    const float* wv = (const float*)d_in[2];
    const float* wq = (const float*)d_in[3];
    float* out = (float*)d_out;

    const int cblocks = (int)((XU + WU) / 256);   // 19456
    convert_all_kernel<<<cblocks, 256>>>(x, wk, wv, wq);

    const long long n_out   = (long long)MM * NS;
    const long long n_state = (long long)BB * NBLK * 64;
    int write_sf = ((long long)out_size >= n_out + n_state) ? 1 : 0;

    cudaFuncSetAttribute(fused_kernel, cudaFuncAttributeMaxDynamicSharedMemorySize, G_SMEM);
    fused_kernel<<<NBLOCKS, 256, G_SMEM>>>(out, write_sf);
}

// round 15
// speedup vs baseline: 1.0947x; 1.0947x over previous
#include <cuda_runtime.h>
#include <cuda_bf16.h>
#include <math.h>
#include <stdint.h>

// Problem constants
#define TT 2048
#define BB 8
#define DD 1024
#define NS 1024
#define NBLK 128
#define MM (TT*BB)        // 16384 projection rows
#define KP 3072           // K' = 3*D  (bf16x3 split concatenated along K)
#define NP 3072           // N' = 3*N_STATE (k,v,q concatenated along N)

// Scratch (device globals: no cudaMalloc allowed)
__device__ __nv_bfloat16 g_A[(size_t)MM * KP];   // [Ah | Ah | Al]
__device__ __nv_bfloat16 g_B[(size_t)NP * KP];   // rows: Wk,Wv,Wq; cols: [Bh | Bl | Bh]
__device__ float         g_P[(size_t)MM * NP];   // cols 0-1023=k, 1024-2047=v, 2048-3071=q

// GEMM tiling — round-13 config: 128x128 tile, 256 threads, 3 stages, 2 CTA/SM
#define GTM 128
#define GTN 128
#define GCK 64
#define G_NCH (KP / GCK)                   // 48
#define STG_BYTES ((GTM + GTN) * GCK * 2)  // 32768 per stage
#define G_SMEM (3 * STG_BYTES)             // 98304 -> 2 CTAs/SM
#define N_NT (NP / GTN)                    // 24 N-tiles per slab
#define N_MT (MM / GTM)                    // 128 M-slabs (16 timesteps each)
#define N_TILES (N_MT * N_NT)              // 3072
#define SCANB 32
#define GEMMB 272

#define XU ((size_t)MM * DD / 4)           // float4 units in x
#define WU ((size_t)3 * NS * DD / 4)       // float4 units in weights

__device__ uint32_t g_tile_ctr;
__device__ uint32_t g_done[N_MT];

// ---------------------------------------------------------------------------
// Helpers
// ---------------------------------------------------------------------------
static __device__ __forceinline__ uint32_t smem_u32(const void* p) {
    uint32_t a;
    asm("{ .reg .u64 t; cvta.to.shared.u64 t, %1; cvt.u32.u64 %0, t; }" : "=r"(a) : "l"(p));
    return a;
}
#define SWZ(off) ((off) ^ (((off) >> 3) & 0x70))

#define CP_ASYNC16(saddr, gaddr) \
    asm volatile("cp.async.cg.shared.global [%0], [%1], 16;" :: "r"(saddr), "l"(gaddr))
#define CP_ASYNC4(saddr, gaddr) \
    asm volatile("cp.async.ca.shared.global [%0], [%1], 4;" :: "r"(saddr), "l"(gaddr))
#define CP_COMMIT() asm volatile("cp.async.commit_group;" ::: "memory")
#define CP_WAIT(n)  asm volatile("cp.async.wait_group %0;" :: "n"(n) : "memory")

#define LDSM_X4(r0, r1, r2, r3, addr) \
    asm volatile("ldmatrix.sync.aligned.m8n8.x4.shared.b16 {%0,%1,%2,%3}, [%4];" \
                 : "=r"(r0), "=r"(r1), "=r"(r2), "=r"(r3) : "r"(addr))

static __device__ __forceinline__ void mma16816(float* d, const uint32_t* a,
                                                const uint32_t* b) {
    asm volatile(
        "mma.sync.aligned.m16n8k16.row.col.f32.bf16.bf16.f32 "
        "{%0,%1,%2,%3}, {%4,%5,%6,%7}, {%8,%9}, {%0,%1,%2,%3};"
        : "+f"(d[0]), "+f"(d[1]), "+f"(d[2]), "+f"(d[3])
        : "r"(a[0]), "r"(a[1]), "r"(a[2]), "r"(a[3]), "r"(b[0]), "r"(b[1]));
}

static __device__ __forceinline__ uint32_t ld_acq(const uint32_t* p) {
    uint32_t v;
    asm volatile("ld.acquire.gpu.global.u32 %0, [%1];" : "=r"(v) : "l"(p) : "memory");
    return v;
}

// Fast-math primitives (MUFU)
static __device__ __forceinline__ float f_tanh(float x)  { float r; asm("tanh.approx.f32 %0, %1;"  : "=f"(r) : "f"(x)); return r; }
static __device__ __forceinline__ float f_rsqrt(float x) { float r; asm("rsqrt.approx.f32 %0, %1;" : "=f"(r) : "f"(x)); return r; }

static __device__ __forceinline__ float dot8(const float* a, const float* b) {
    float p = a[0]*b[0]; p = fmaf(a[1],b[1],p); p = fmaf(a[2],b[2],p); p = fmaf(a[3],b[3],p);
    float q = a[4]*b[4]; q = fmaf(a[5],b[5],q); q = fmaf(a[6],b[6],q); q = fmaf(a[7],b[7],q);
    return p + q;
}

// ---------------------------------------------------------------------------
// Conversion (merged x + weights): fp32 -> bf16 hi/lo split, K-concatenated
// ---------------------------------------------------------------------------
static __device__ __forceinline__ uint2 pack4(const float* f, bool lo_part) {
    unsigned short h[4];
#pragma unroll
    for (int j = 0; j < 4; j++) {
        __nv_bfloat16 hi = __float2bfloat16(f[j]);
        if (!lo_part) h[j] = __bfloat16_as_ushort(hi);
        else          h[j] = __bfloat16_as_ushort(__float2bfloat16(f[j] - __bfloat162float(hi)));
    }
    uint2 r;
    r.x = (uint32_t)h[0] | ((uint32_t)h[1] << 16);
    r.y = (uint32_t)h[2] | ((uint32_t)h[3] << 16);
    return r;
}

__global__ void __launch_bounds__(256)
convert_all_kernel(const float* __restrict__ X, const float* __restrict__ Wk,
                   const float* __restrict__ Wv, const float* __restrict__ Wq) {
    // reset producer-consumer state for this graph replay
    if (blockIdx.x == 0) {
        if (threadIdx.x == 0) g_tile_ctr = 0;
        if (threadIdx.x < N_MT) g_done[threadIdx.x] = 0;
    }
    size_t i = (size_t)blockIdx.x * 256 + threadIdx.x;
    if (i < XU) {
        size_t e = i * 4;
        size_t m = e / DD;
        int    c = (int)(e % DD);
        float4 a = *(const float4*)(X + e);
        float f[4] = {a.x, a.y, a.z, a.w};
        uint2 hp = pack4(f, false);
        uint2 lp = pack4(f, true);
        __nv_bfloat16* row = g_A + m * KP;
        *(uint2*)(row + c)        = hp;
        *(uint2*)(row + c + DD)   = hp;
        *(uint2*)(row + c + 2*DD) = lp;
    } else {
        size_t e = (i - XU) * 4;
        int    w = (int)(e / ((size_t)NS * DD));
        size_t r = e % ((size_t)NS * DD);
        const float* W = (w == 0) ? Wk : ((w == 1) ? Wv : Wq);
        size_t n = r / DD;
        int    c = (int)(r % DD);
        float4 a = *(const float4*)(W + r);
        float f[4] = {a.x, a.y, a.z, a.w};
        uint2 hp = pack4(f, false);
        uint2 lp = pack4(f, true);
        __nv_bfloat16* row = g_B + ((size_t)w * NS + n) * KP;
        *(uint2*)(row + c)        = hp;
        *(uint2*)(row + c + DD)   = lp;
        *(uint2*)(row + c + 2*DD) = hp;
    }
}

// ---------------------------------------------------------------------------
// FUSED persistent kernel (round-13 config). Blocks 0..31: scan consumers.
// Blocks 32..303: persistent GEMM workers, 128x128 tiles, 2 CTAs/SM, with
// intra-chunk LDSM/MMA double-buffering (frags of step s+1 load under MMAs
// of step s). GEMM never waits on scan => no deadlock.
// ---------------------------------------------------------------------------
#define SDEPTH 16

__global__ void __launch_bounds__(256, 2)
fused_kernel(float* __restrict__ out, int write_sf)
{
    extern __shared__ char smem[];
    __shared__ int s_tile;
    const int tid = threadIdx.x;

    if (blockIdx.x >= SCANB) {
        // =================== GEMM worker =====================================
        const uint32_t sb = smem_u32(smem);
        const int wid = tid >> 5;
        const int lid = tid & 31;
        const int wm = wid & 1;
        const int wn = wid >> 1;
        const int lrow  = (lid & 7) + ((lid >> 3) & 1) * 8;
        const int chalf = lid >> 4;

        for (;;) {
            __syncthreads();             // smem stages + s_tile safe to reuse
            if (tid == 0) s_tile = (int)atomicAdd(&g_tile_ctr, 1u);
            __syncthreads();
            const int tile = s_tile;
            if (tile >= N_TILES) break;
            const int mt = tile / N_NT;
            const int nt = tile - mt * N_NT;
            const size_t bm = (size_t)mt * GTM;
            const size_t bn = (size_t)nt * GTN;
            const __nv_bfloat16* Abase = g_A + bm * KP;
            const __nv_bfloat16* Bbase = g_B + bn * KP;

            auto issue_stage = [&](int i) {
                const uint32_t abuf = sb + (i % 3) * STG_BYTES;
                const uint32_t bbuf = abuf + GTM * GCK * 2;
                const __nv_bfloat16* As = Abase + i * GCK;
                const __nv_bfloat16* Bs = Bbase + i * GCK;
#pragma unroll
                for (int u = 0; u < 4; u++) {
                    int unit = tid + u * 256;
                    int r = unit >> 3, c = unit & 7;
                    uint32_t off = SWZ(r * 128 + c * 16);
                    CP_ASYNC16(abuf + off, (const char*)(As + (size_t)r * KP + c * 8));
                    CP_ASYNC16(bbuf + off, (const char*)(Bs + (size_t)r * KP + c * 8));
                }
                CP_COMMIT();
            };

            issue_stage(0);
            issue_stage(1);

            float acc[4][4][4];
#pragma unroll
            for (int i = 0; i < 4; i++)
#pragma unroll
                for (int j = 0; j < 4; j++)
#pragma unroll
                    for (int r = 0; r < 4; r++) acc[i][j][r] = 0.0f;

            auto load_frags = [&](uint32_t abuf, uint32_t bbuf, int s,
                                  uint32_t a[4][4], uint32_t b[2][4]) {
                const int ch = 2 * s + chalf;
#pragma unroll
                for (int mf = 0; mf < 4; mf++) {
                    uint32_t addr = abuf + SWZ((wm * 64 + mf * 16 + lrow) * 128 + ch * 16);
                    LDSM_X4(a[mf][0], a[mf][1], a[mf][2], a[mf][3], addr);
                }
#pragma unroll
                for (int nf2 = 0; nf2 < 2; nf2++) {
                    uint32_t addr = bbuf + SWZ((wn * 32 + nf2 * 16 + lrow) * 128 + ch * 16);
                    LDSM_X4(b[nf2][0], b[nf2][1], b[nf2][2], b[nf2][3], addr);
                }
            };
            auto do_mmas = [&](uint32_t a[4][4], uint32_t b[2][4]) {
#pragma unroll
                for (int mf = 0; mf < 4; mf++) {
#pragma unroll
                    for (int nf = 0; nf < 4; nf++) {
                        uint32_t bb_[2] = { b[nf >> 1][(nf & 1)], b[nf >> 1][(nf & 1) + 2] };
                        mma16816(acc[mf][nf], a[mf], bb_);
                    }
                }
            };

            for (int it = 0; it < G_NCH; it++) {
                CP_WAIT(1);
                __syncthreads();
                if (it + 2 < G_NCH) issue_stage(it + 2);
                else CP_COMMIT();

                const uint32_t abuf = sb + (it % 3) * STG_BYTES;
                const uint32_t bbuf = abuf + GTM * GCK * 2;

                // intra-chunk double buffering: frags(s+1) load under MMAs(s)
                uint32_t a0[4][4], b0[2][4], a1[4][4], b1[2][4];
                load_frags(abuf, bbuf, 0, a0, b0);
#pragma unroll
                for (int s = 0; s < 4; s++) {
                    if (s < 3) {
                        if (s & 1) load_frags(abuf, bbuf, s + 1, a0, b0);
                        else       load_frags(abuf, bbuf, s + 1, a1, b1);
                    }
                    if (s & 1) do_mmas(a1, b1);
                    else       do_mmas(a0, b0);
                }
            }

            // epilogue + release
            const int r0 = lid >> 2;
            const int cp = (lid & 3) * 2;
#pragma unroll
            for (int mf = 0; mf < 4; mf++) {
#pragma unroll
                for (int nf = 0; nf < 4; nf++) {
                    float* dst = g_P + (bm + wm * 64 + mf * 16 + r0) * (size_t)NP
                                     + bn + wn * 32 + nf * 8 + cp;
                    *(float2*)dst = make_float2(acc[mf][nf][0], acc[mf][nf][1]);
                    *(float2*)(dst + 8 * NP) = make_float2(acc[mf][nf][2], acc[mf][nf][3]);
                }
            }
            __threadfence();
            __syncthreads();
            if (tid == 0)
                asm volatile("red.release.gpu.global.add.u32 [%0], 1;"
                             :: "l"(&g_done[mt]) : "memory");
        }
        return;
    }

    // =================== scan consumer: 32 chains, 8 warps ==================
    const int sblk = blockIdx.x;     // 0..31
    const int w    = tid >> 5;       // 0..7
    const int l    = tid & 31;
    const int lane = tid & 7;
    const int c    = sblk * 32 + (tid >> 3);
    const int b    = sblk >> 2;
    const int nb   = c & 127;
    const int col0 = (sblk & 3) * 256 + w * 32;
    const size_t pstep = (size_t)BB * NP;

    float* dsm = (float*)smem;
    const uint32_t rb = smem_u32(smem) + w * 384;   // warp slice: 96 floats
    const float* myslice = dsm + w * 96;
    const int ch8 = l & 24;

    const float* src = g_P + (size_t)b * NP + col0;

    auto issue = [&](int t) {
        const float* sp = src + (size_t)t * pstep;
        uint32_t st = rb + (t & (SDEPTH - 1)) * 3072;   // 8 warps * 384B per stage
        CP_ASYNC4(st + l * 4,       (const char*)(sp + l));
        CP_ASYNC4(st + 128 + l * 4, (const char*)(sp + NS + l));
        CP_ASYNC4(st + 256 + l * 4, (const char*)(sp + 2 * NS + l));
        CP_COMMIT();
    };

    auto load_prep = [&](int t, float* kn, float* qc, float& vv) {
        const float* fs = myslice + (t & (SDEPTH - 1)) * 768;
        float4 k0 = *(const float4*)(fs + ch8);
        float4 k1 = *(const float4*)(fs + ch8 + 4);
        float4 q0 = *(const float4*)(fs + 64 + ch8);
        float4 q1 = *(const float4*)(fs + 64 + ch8 + 4);
        vv = fs[32 + ch8 + lane];
        float kc[8] = {k0.x,k0.y,k0.z,k0.w,k1.x,k1.y,k1.z,k1.w};
        float ss  = dot8(kc, kc);
        float inv = f_rsqrt(ss + 1e-12f);   // == 1/(||k||+1e-6) to ~3.5e-7 rel
#pragma unroll
        for (int j = 0; j < 8; j++) kn[j] = kc[j] * inv;
        qc[0]=q0.x; qc[1]=q0.y; qc[2]=q0.z; qc[3]=q0.w;
        qc[4]=q1.x; qc[5]=q1.y; qc[6]=q1.z; qc[7]=q1.w;
    };

    int ready = -1;
    auto wait_slab = [&](int t) {
        int need = t >> 4;           // 16 timesteps per 128-row slab
        if (need > ready) {
            while (ld_acq(&g_done[need]) < (uint32_t)N_NT) __nanosleep(64);
            ready = need;
        }
    };

    float* op = out + (size_t)b * NS + nb * 8 + lane;
    const int ostride = BB * NS;

    float S[8];
#pragma unroll
    for (int j = 0; j < 8; j++) S[j] = 0.0f;

    // prologue: wait first slabs, then 14 stages in flight
    wait_slab(13);
    for (int st = 0; st < 14; st++) issue(st);
    CP_WAIT(13);
    __syncwarp();

    float knA[8], qcA[8], vvA, knB[8], qcB[8], vvB;
    load_prep(0, knA, qcA, vvA);

    auto step = [&](int t, const float* kn, const float* qc, float vv,
                    float* knN, float* qcN, float& vvN) {
        if (t + 14 < TT) { wait_slab(t + 14); issue(t + 14); }
        else CP_COMMIT();

        // --- S critical chain: retrieve -> delta -> HW tanh ---
        float r = dot8(S, kn);
        float delta = vv - r;
#pragma unroll
        for (int j = 0; j < 8; j++)
            S[j] = f_tanh(fmaf(delta, kn[j], S[j]));

        // --- fill tanh latency: advance pipeline + prep t+1 ---
        CP_WAIT(13);
        __syncwarp();
        if (t + 1 < TT) load_prep(t + 1, knN, qcN, vvN);

        // --- output for t: silu sigmoid via HW tanh ---
        float sq  = dot8(S, qc);
        float sig = fmaf(0.5f, f_tanh(0.5f * sq), 0.5f);
        op[(size_t)t * ostride] = sq * sq * sig;
    };

    for (int t = 0; t < TT; t += 2) {
        step(t,     knA, qcA, vvA, knB, qcB, vvB);
        step(t + 1, knB, qcB, vvB, knA, qcA, vvA);
    }

    if (write_sf) {
        float* sf = out + (size_t)MM * NS + (size_t)c * 64 + lane * 8;
#pragma unroll
        for (int j = 0; j < 8; j++) sf[j] = S[j];
    }
}

// ---------------------------------------------------------------------------
extern "C" void kernel_launch(void* const* d_in, const int* in_sizes, int n_in,
                              void* d_out, int out_size)
{
    (void)in_sizes; (void)n_in;
    const float* x  = (const float*)d_in[0];
    const float* wk = (const float*)d_in[1];
    const float* wv = (const float*)d_in[2];
    const float* wq = (const float*)d_in[3];
    float* out = (float*)d_out;

    const int cblocks = (int)((XU + WU) / 256);   // 19456
    convert_all_kernel<<<cblocks, 256>>>(x, wk, wv, wq);

    const long long n_out   = (long long)MM * NS;
    const long long n_state = (long long)BB * NBLK * 64;
    int write_sf = ((long long)out_size >= n_out + n_state) ? 1 : 0;

    cudaFuncSetAttribute(fused_kernel, cudaFuncAttributeMaxDynamicSharedMemorySize, G_SMEM);
    fused_kernel<<<SCANB + GEMMB, 256, G_SMEM>>>(out, write_sf);
}